// round 1
// baseline (speedup 1.0000x reference)
#include <cuda_runtime.h>
#include <cuda_bf16.h>
#include <math.h>

// Problem constants
#define BSZ   8
#define NQ    900
#define DIM   256
#define TOPK  10
#define NROWS (BSZ*NQ)            // 7200
#define KF    264                 // folded feature dim: 1 + 256, padded to mult of 8
#define MAXM  (NROWS*TOPK)        // 72000

// Scratch (static device globals; no allocation)
__device__ int   g_cnt;
__device__ int   g_list[NROWS];          // active (b,i) rows (compacted)
__device__ int   g_nidx[MAXM];           // neighbor global row (b*NQ + j)
__device__ float g_niou[MAXM];           // gathered overlap value
__device__ float g_nmk [MAXM];           // mk (0/1)
__device__ float g_W3f[KF*DIM];          // folded W3: [264][256]
__device__ float g_F  [(size_t)MAXM*KF]; // folded features
__device__ float g_Hb [(size_t)MAXM*DIM];// relu(F@W3f+b3)
__device__ float g_Fe [(size_t)MAXM*DIM];// H@W4+b4
__device__ float g_T1 [(size_t)NROWS*DIM];
__device__ float g_CT [(size_t)NROWS*DIM];
__device__ float g_AG [(size_t)NROWS*DIM];

// ---------------------------------------------------------------- zero + cnt
__global__ void zero_kernel(float* __restrict__ out){
    int i = blockIdx.x*blockDim.x + threadIdx.x;
    if (i == 0) g_cnt = 0;
    if (i < NROWS*DIM) out[i] = 0.f;
}

// ---------------------------------------------------------------- fold W3
// features col layout (folded, width 257):
//   col 0            : overs scalar (v*mk), matched against sum of W3 rows 0..63
//   col 1 + a*128 + s*64 + m : wave value at (a,s,d=2m)==(a,s,d=2m+1)
//   -> W3f row = W3[64 + a*256 + s*128 + 2m] + W3[64 + a*256 + s*128 + 2m+1]
__global__ void prep_kernel(const float* __restrict__ W3){
    int r = blockIdx.x, c = threadIdx.x;
    float v = 0.f;
    if (r == 0){
        #pragma unroll 8
        for (int q = 0; q < 64; q++) v += W3[q*DIM + c];
    } else if (r <= 256){
        int q = r-1, a = q>>7, rem = q&127, sc = rem>>6, m = rem&63;
        int j = 64 + a*256 + sc*128 + 2*m;
        v = W3[j*DIM + c] + W3[(j+1)*DIM + c];
    }
    g_W3f[r*DIM + c] = v;
}

// ---------------------------------------------------------------- top-K
// One warp per (b,i) row. Key packs (value_bits << 32) | (~j) so ties break
// toward the smaller index, matching stable argsort of -overlaps.
__global__ void topk_kernel(const float* __restrict__ ious,
                            const float* __restrict__ gmask){
    int warp = threadIdx.x >> 5, lane = threadIdx.x & 31;
    int r = blockIdx.x*8 + warp;
    if (r >= NROWS) return;
    if (gmask[r] != 0.f) return;           // neg==0 -> row inactive, output 0
    int b = r / NQ;
    const float* row  = ious + (size_t)r*NQ;
    const float* mrow = gmask + b*NQ;

    unsigned long long loc[TOPK];
    #pragma unroll
    for (int t = 0; t < TOPK; t++) loc[t] = 0ull;

    for (int j = lane; j < NQ; j += 32){
        float v = row[j] * mrow[j];        // overlaps (neg_i == 1)
        unsigned long long key =
            ((unsigned long long)__float_as_uint(v) << 32) |
            (unsigned)(0xFFFFFFFFu - (unsigned)j);
        if (key > loc[TOPK-1]){
            loc[TOPK-1] = key;
            #pragma unroll
            for (int t = TOPK-1; t > 0; t--){
                if (loc[t] > loc[t-1]){
                    unsigned long long tmp = loc[t-1]; loc[t-1] = loc[t]; loc[t] = tmp;
                }
            }
        }
    }
    int pos = 0;
    if (lane == 0){ pos = atomicAdd(&g_cnt, 1); g_list[pos] = r; }
    pos = __shfl_sync(0xffffffffu, pos, 0);

    for (int t = 0; t < TOPK; t++){
        unsigned long long cand = loc[0];
        unsigned long long best = cand;
        #pragma unroll
        for (int o = 16; o > 0; o >>= 1){
            unsigned long long oth = __shfl_xor_sync(0xffffffffu, best, o);
            if (oth > best) best = oth;
        }
        if (cand == best){                 // unique key -> exactly one lane pops
            #pragma unroll
            for (int t2 = 0; t2 < TOPK-1; t2++) loc[t2] = loc[t2+1];
            loc[TOPK-1] = 0ull;
        }
        if (lane == 0){
            unsigned j = 0xFFFFFFFFu - (unsigned)(best & 0xFFFFFFFFull);
            float v = __uint_as_float((unsigned)(best >> 32));
            g_nidx[pos*TOPK + t] = b*NQ + (int)j;
            g_niou[pos*TOPK + t] = v;
            g_nmk [pos*TOPK + t] = (mrow[j] != 0.f && v >= 0.4f) ? 1.f : 0.f;
        }
    }
}

// ---------------------------------------------------------------- features
// Builds folded feature rows. sinpif/cospif: exact range reduction, safe
// under fast-math, args up to ~32 "pi units".
__global__ void feat_kernel(const float* __restrict__ bboxes){
    int g = blockIdx.x;
    if (g >= g_cnt) return;
    int tid = threadIdx.x;
    __shared__ float P[TOPK][4];
    __shared__ float MK[TOPK];

    if (tid < TOPK){
        int k = tid;
        int srow = g_list[g];
        float4 sb = *(const float4*)(bboxes + (size_t)srow*4);
        int nrow = g_nidx[g*TOPK + k];
        float4 nb = *(const float4*)(bboxes + (size_t)nrow*4);
        float mkv = g_nmk[g*TOPK + k];
        MK[k] = mkv;
        float dcx = 0.5f*(nb.x+nb.z) - 0.5f*(sb.x+sb.z);
        float dcy = 0.5f*(nb.y+nb.w) - 0.5f*(sb.y+sb.w);
        float dwx = (nb.z-nb.x) - (sb.z-sb.x);
        float dwy = (nb.w-nb.y) - (sb.w-sb.y);
        // pre-multiplied by 2 so angle (in units of pi) = P * 10000^{-m/64}
        P[k][0] = 2.f*logf(fmaxf(fabsf(dcx), 1e-7f));
        P[k][1] = 2.f*logf(fmaxf(fabsf(dcy), 1e-7f));
        P[k][2] = 2.f*logf(fmaxf(fabsf(dwx), 1e-7f));
        P[k][3] = 2.f*logf(fmaxf(fabsf(dwy), 1e-7f));
        float* fr = g_F + ((size_t)g*TOPK + k)*KF;
        fr[0] = g_niou[g*TOPK + k] * mkv;
        #pragma unroll
        for (int c = 257; c < KF; c++) fr[c] = 0.f;   // padding
    }
    __syncthreads();

    for (int item = tid; item < TOPK*64; item += blockDim.x){
        int k = item >> 6, m = item & 63;
        float* fr = g_F + ((size_t)g*TOPK + k)*KF + 1;
        if (MK[k] == 0.f){
            fr[m] = 0.f; fr[64+m] = 0.f; fr[128+m] = 0.f; fr[192+m] = 0.f;
        } else {
            // 1/dim_t = 10000^(-m/64); log2(10000)/64
            float invt = exp2f(-(float)m * 0.20762050593045977f);
            fr[m]       = sinpif(P[k][0]*invt);
            fr[64 + m]  = cospif(P[k][1]*invt);
            fr[128 + m] = sinpif(P[k][2]*invt);
            fr[192 + m] = cospif(P[k][3]*invt);
        }
    }
}

// ---------------------------------------------------------------- masked max over K
__global__ void agg_kernel(){
    int g = blockIdx.x;
    if (g >= g_cnt) return;
    int c = threadIdx.x;
    float best = g_Fe[((size_t)g*TOPK + 0)*DIM + c] * g_nmk[g*TOPK + 0];
    #pragma unroll
    for (int k = 1; k < TOPK; k++)
        best = fmaxf(best, g_Fe[((size_t)g*TOPK + k)*DIM + c] * g_nmk[g*TOPK + k]);
    g_AG[(size_t)g*DIM + c] = best;
}

// ---------------------------------------------------------------- generic sgemm
// C[m,n] = op( A[m,:] @ B[:,n] + bias[n] (+ AGG[m,n]) ), dynamic M = g_cnt*ROWMULT
// BM=BN=128, BK=8, 256 threads, 8x8 per-thread tile.
// ASEL: 0=ext 1=g_F 2=g_Hb 3=g_T1 4=g_CT ; BSEL: 0=ext 1=g_W3f
// CSEL: 0=ext 1=g_Hb 2=g_Fe 3=g_T1 4=g_CT
template<int KDIM, int ROWMULT, int ASEL, int BSEL, int CSEL,
         bool GATHER, bool RELU, bool ADDV, bool SCATTER>
__global__ void __launch_bounds__(256) sgemm_kernel(
    const float* __restrict__ Aext, int lda,
    const float* __restrict__ Bext,
    const float* __restrict__ bias,
    float* __restrict__ Cext)
{
    const float* A = (ASEL==0)?Aext : (ASEL==1)?g_F : (ASEL==2)?g_Hb : (ASEL==3)?g_T1 : g_CT;
    const float* B = (BSEL==0)?Bext : g_W3f;
    float*       C = (CSEL==0)?Cext : (CSEL==1)?g_Hb : (CSEL==2)?g_Fe : (CSEL==3)?g_T1 : g_CT;

    int rows = g_cnt * ROWMULT;
    int m0 = blockIdx.x * 128;
    if (m0 >= rows) return;
    int n0 = blockIdx.y * 128;

    __shared__ float As[8][128];
    __shared__ float Bs[8][128];

    int tid = threadIdx.x;
    int tx = tid & 15;      // n direction
    int ty = tid >> 4;      // m direction
    int arow = tid >> 1;
    int ak   = (tid & 1) * 4;
    int brow = tid >> 5;
    int bn   = (tid & 31) * 4;

    float acc[8][8];
    #pragma unroll
    for (int i = 0; i < 8; i++)
        #pragma unroll
        for (int j = 0; j < 8; j++) acc[i][j] = 0.f;

    for (int k0 = 0; k0 < KDIM; k0 += 8){
        float4 av = make_float4(0.f,0.f,0.f,0.f);
        int am = m0 + arow;
        if (am < rows){
            int ga = GATHER ? g_list[am] : am;
            av = *(const float4*)(A + (size_t)ga*lda + k0 + ak);
        }
        float4 bv = *(const float4*)(B + (size_t)(k0+brow)*DIM + n0 + bn);
        __syncthreads();
        As[ak+0][arow] = av.x; As[ak+1][arow] = av.y;
        As[ak+2][arow] = av.z; As[ak+3][arow] = av.w;
        *(float4*)&Bs[brow][bn] = bv;
        __syncthreads();
        #pragma unroll
        for (int kk = 0; kk < 8; kk++){
            float ar[8], br[8];
            #pragma unroll
            for (int i = 0; i < 8; i++) ar[i] = As[kk][ty*8 + i];
            #pragma unroll
            for (int j = 0; j < 8; j++) br[j] = Bs[kk][tx*8 + j];
            #pragma unroll
            for (int i = 0; i < 8; i++)
                #pragma unroll
                for (int j = 0; j < 8; j++) acc[i][j] += ar[i]*br[j];
        }
    }

    #pragma unroll
    for (int i = 0; i < 8; i++){
        int m = m0 + ty*8 + i;
        if (m >= rows) break;
        int crow = SCATTER ? g_list[m] : m;
        #pragma unroll
        for (int j = 0; j < 8; j += 4){
            int n = n0 + tx*8 + j;
            float4 r;
            r.x = acc[i][j+0] + bias[n+0];
            r.y = acc[i][j+1] + bias[n+1];
            r.z = acc[i][j+2] + bias[n+2];
            r.w = acc[i][j+3] + bias[n+3];
            if (ADDV){
                float4 avv = *(const float4*)(g_AG + (size_t)m*DIM + n);
                r.x += avv.x; r.y += avv.y; r.z += avv.z; r.w += avv.w;
            }
            if (RELU){
                r.x = fmaxf(r.x,0.f); r.y = fmaxf(r.y,0.f);
                r.z = fmaxf(r.z,0.f); r.w = fmaxf(r.w,0.f);
            }
            *(float4*)(C + (size_t)crow*DIM + n) = r;
        }
    }
}

// ---------------------------------------------------------------- launch
extern "C" void kernel_launch(void* const* d_in, const int* in_sizes, int n_in,
                              void* d_out, int out_size){
    const float* tgt    = (const float*)d_in[0];
    const float* ious   = (const float*)d_in[1];
    const float* bboxes = (const float*)d_in[2];
    const float* gmask  = (const float*)d_in[3];
    const float* W1 = (const float*)d_in[4];  const float* b1 = (const float*)d_in[5];
    const float* W2 = (const float*)d_in[6];  const float* b2 = (const float*)d_in[7];
    const float* W3 = (const float*)d_in[8];  const float* b3 = (const float*)d_in[9];
    const float* W4 = (const float*)d_in[10]; const float* b4 = (const float*)d_in[11];
    const float* W5 = (const float*)d_in[12]; const float* b5 = (const float*)d_in[13];
    float* out = (float*)d_out;

    (void)in_sizes; (void)n_in; (void)out_size;

    zero_kernel<<<NROWS, 256>>>(out);           // also resets g_cnt
    prep_kernel<<<KF, 256>>>(W3);
    topk_kernel<<<NQ, 256>>>(ious, gmask);
    feat_kernel<<<NROWS, 256>>>(bboxes);

    dim3 gBig  ((MAXM  + 127)/128, 2);
    dim3 gSmall((NROWS + 127)/128, 2);

    // H = relu(F @ W3f + b3)
    sgemm_kernel<KF , TOPK, 1, 1, 1, false, true , false, false><<<gBig, 256>>>(nullptr, KF , nullptr, b3, nullptr);
    // FEAT = H @ W4 + b4
    sgemm_kernel<DIM, TOPK, 2, 0, 2, false, false, false, false><<<gBig, 256>>>(nullptr, DIM, W4, b4, nullptr);
    // AGG = max_k(FEAT * mk)
    agg_kernel<<<NROWS, 256>>>();
    // T1 = relu(tgt[list] @ W1 + b1)
    sgemm_kernel<DIM, 1, 0, 0, 3, true , true , false, false><<<gSmall, 256>>>(tgt, DIM, W1, b1, nullptr);
    // CT = T1 @ W2 + b2 + AGG   (neg==1 on active rows)
    sgemm_kernel<DIM, 1, 3, 0, 4, false, false, true , false><<<gSmall, 256>>>(nullptr, DIM, W2, b2, nullptr);
    // out[list] = relu(CT @ W5 + b5)
    sgemm_kernel<DIM, 1, 4, 0, 0, false, true , false, true ><<<gSmall, 256>>>(nullptr, DIM, W5, b5, out);
}

// round 3
// speedup vs baseline: 1.8998x; 1.8998x over previous
#include <cuda_runtime.h>
#include <cuda_bf16.h>
#include <math.h>
#include <stdint.h>

// ---------------------------------------------------------------- constants
#define BSZ   8
#define NQ    900
#define DIM   256
#define TOPK  10
#define NROWS (BSZ*NQ)            // 7200
#define MAXM  (NROWS*TOPK)        // 72000
#define MAXM_PAD  72064           // 563*128
#define NROWS_PAD 7296            // 57*128

// smem GEMM tiles: 4 tiles (Ahi,Alo,Bhi,Blo) of 128 rows x 32 bf16, row pad to 40
#define TILE_BYTES 10240          // 128*80
#define BUF_BYTES  40960          // 4 tiles
#define SMEM_SZ    81920          // double buffered

// ---------------------------------------------------------------- scratch
__device__ int   g_cnt;
__device__ int   g_list[NROWS];
__device__ int   g_nidx[MAXM];
__device__ float g_niou[MAXM];
__device__ float g_nmk [MAXM];
__device__ float g_overs[MAXM];
__device__ float g_w3sum[DIM];

__device__ __nv_bfloat16 g_Bwhi[5*DIM*DIM];  // weights [w][n][k] K-major
__device__ __nv_bfloat16 g_Bwlo[5*DIM*DIM];

__device__ __nv_bfloat16 g_Fhi [(size_t)MAXM_PAD*DIM];
__device__ __nv_bfloat16 g_Flo [(size_t)MAXM_PAD*DIM];
__device__ __nv_bfloat16 g_Hhi [(size_t)MAXM_PAD*DIM];
__device__ __nv_bfloat16 g_Hlo [(size_t)MAXM_PAD*DIM];
__device__ __nv_bfloat16 g_A3hi[(size_t)NROWS_PAD*DIM];
__device__ __nv_bfloat16 g_A3lo[(size_t)NROWS_PAD*DIM];
__device__ __nv_bfloat16 g_T1hi[(size_t)NROWS_PAD*DIM];
__device__ __nv_bfloat16 g_T1lo[(size_t)NROWS_PAD*DIM];
__device__ __nv_bfloat16 g_CThi[(size_t)NROWS_PAD*DIM];
__device__ __nv_bfloat16 g_CTlo[(size_t)NROWS_PAD*DIM];
__device__ float g_Fe[(size_t)MAXM*DIM];
__device__ float g_AG[(size_t)NROWS*DIM];

// ---------------------------------------------------------------- helpers
static __device__ __forceinline__ uint32_t smem_u32(const void* p){
    uint32_t a;
    asm("{ .reg .u64 t; cvta.to.shared.u64 t, %1; cvt.u32.u64 %0, t; }" : "=r"(a) : "l"(p));
    return a;
}
static __device__ __forceinline__ void cp_async16(uint32_t s, const void* g){
    asm volatile("cp.async.ca.shared.global [%0], [%1], 16;" :: "r"(s), "l"(g));
}
static __device__ __forceinline__ void cp_commit(){
    asm volatile("cp.async.commit_group;");
}
template<int N> static __device__ __forceinline__ void cp_wait(){
    asm volatile("cp.async.wait_group %0;" :: "n"(N));
}
#define LDMATRIX_X4(r, addr) \
    asm volatile("ldmatrix.sync.aligned.m8n8.x4.shared.b16 {%0,%1,%2,%3}, [%4];" \
        : "=r"((r)[0]), "=r"((r)[1]), "=r"((r)[2]), "=r"((r)[3]) : "r"(addr))
#define LDMATRIX_X2(r, addr) \
    asm volatile("ldmatrix.sync.aligned.m8n8.x2.shared.b16 {%0,%1}, [%2];" \
        : "=r"((r)[0]), "=r"((r)[1]) : "r"(addr))
#define MMA_BF16(c, a, b) \
    asm volatile("mma.sync.aligned.m16n8k16.row.col.f32.bf16.bf16.f32 " \
        "{%0,%1,%2,%3}, {%4,%5,%6,%7}, {%8,%9}, {%0,%1,%2,%3};" \
        : "+f"((c)[0]), "+f"((c)[1]), "+f"((c)[2]), "+f"((c)[3]) \
        : "r"((a)[0]), "r"((a)[1]), "r"((a)[2]), "r"((a)[3]), "r"((b)[0]), "r"((b)[1]))

static __device__ __forceinline__ void bsplit(float v, __nv_bfloat16& h, __nv_bfloat16& l){
    h = __float2bfloat16(v);
    l = __float2bfloat16(v - __bfloat162float(h));
}

// ---------------------------------------------------------------- zero + cnt
__global__ void zero_kernel(float* __restrict__ out){
    int i = blockIdx.x*blockDim.x + threadIdx.x;
    if (i == 0) g_cnt = 0;
    if (i < NROWS*DIM) out[i] = 0.f;
}

// ---------------------------------------------------------------- weight prep
__global__ void prep_kernel(const float* __restrict__ W1, const float* __restrict__ W2,
                            const float* __restrict__ W3, const float* __restrict__ W4,
                            const float* __restrict__ W5){
    int k = threadIdx.x, n = blockIdx.x, w = blockIdx.y;
    const float* W = (w==0)?W1 : (w==1)?W2 : (w==2)?W3 : (w==3)?W4 : W5;
    float v;
    if (w == 2){
        int a = k>>7, s = (k>>6)&1, m = k&63;
        int j = 64 + a*256 + s*128 + 2*m;
        v = W[j*DIM + n] + W[(j+1)*DIM + n];
    } else {
        v = W[k*DIM + n];
    }
    __nv_bfloat16 h, l; bsplit(v, h, l);
    g_Bwhi[(size_t)w*DIM*DIM + n*DIM + k] = h;
    g_Bwlo[(size_t)w*DIM*DIM + n*DIM + k] = l;
}
__global__ void w3sum_kernel(const float* __restrict__ W3){
    int n = threadIdx.x;
    float s = 0.f;
    #pragma unroll 8
    for (int q = 0; q < 64; q++) s += W3[q*DIM + n];
    g_w3sum[n] = s;
}

// ---------------------------------------------------------------- top-K
__global__ void topk_kernel(const float* __restrict__ ious,
                            const float* __restrict__ gmask){
    int warp = threadIdx.x >> 5, lane = threadIdx.x & 31;
    int r = blockIdx.x*8 + warp;
    if (r >= NROWS) return;
    if (gmask[r] != 0.f) return;
    int b = r / NQ;
    const float* row  = ious + (size_t)r*NQ;
    const float* mrow = gmask + b*NQ;

    unsigned long long loc[TOPK];
    #pragma unroll
    for (int t = 0; t < TOPK; t++) loc[t] = 0ull;

    for (int j = lane; j < NQ; j += 32){
        float v = row[j] * mrow[j];
        unsigned long long key =
            ((unsigned long long)__float_as_uint(v) << 32) |
            (unsigned)(0xFFFFFFFFu - (unsigned)j);
        if (key > loc[TOPK-1]){
            loc[TOPK-1] = key;
            #pragma unroll
            for (int t = TOPK-1; t > 0; t--)
                if (loc[t] > loc[t-1]){
                    unsigned long long tmp = loc[t-1]; loc[t-1] = loc[t]; loc[t] = tmp;
                }
        }
    }
    int pos = 0;
    if (lane == 0){ pos = atomicAdd(&g_cnt, 1); g_list[pos] = r; }
    pos = __shfl_sync(0xffffffffu, pos, 0);

    for (int t = 0; t < TOPK; t++){
        unsigned long long cand = loc[0];
        unsigned long long best = cand;
        #pragma unroll
        for (int o = 16; o > 0; o >>= 1){
            unsigned long long oth = __shfl_xor_sync(0xffffffffu, best, o);
            if (oth > best) best = oth;
        }
        if (cand == best){
            #pragma unroll
            for (int t2 = 0; t2 < TOPK-1; t2++) loc[t2] = loc[t2+1];
            loc[TOPK-1] = 0ull;
        }
        if (lane == 0){
            unsigned j = 0xFFFFFFFFu - (unsigned)(best & 0xFFFFFFFFull);
            float v = __uint_as_float((unsigned)(best >> 32));
            g_nidx[pos*TOPK + t] = b*NQ + (int)j;
            g_niou[pos*TOPK + t] = v;
            g_nmk [pos*TOPK + t] = (mrow[j] != 0.f && v >= 0.4f) ? 1.f : 0.f;
        }
    }
}

// ---------------------------------------------------------------- features (bf16 hi/lo)
__global__ void feat_kernel(const float* __restrict__ bboxes){
    int g = blockIdx.x;
    if (g >= g_cnt) return;
    int tid = threadIdx.x;
    __shared__ float P[TOPK][4];
    __shared__ float MK[TOPK];

    if (tid < TOPK){
        int k = tid;
        int srow = g_list[g];
        float4 sb = *(const float4*)(bboxes + (size_t)srow*4);
        int nrow = g_nidx[g*TOPK + k];
        float4 nb = *(const float4*)(bboxes + (size_t)nrow*4);
        float mkv = g_nmk[g*TOPK + k];
        MK[k] = mkv;
        g_overs[g*TOPK + k] = g_niou[g*TOPK + k] * mkv;
        float dcx = 0.5f*(nb.x+nb.z) - 0.5f*(sb.x+sb.z);
        float dcy = 0.5f*(nb.y+nb.w) - 0.5f*(sb.y+sb.w);
        float dwx = (nb.z-nb.x) - (sb.z-sb.x);
        float dwy = (nb.w-nb.y) - (sb.w-sb.y);
        P[k][0] = 2.f*logf(fmaxf(fabsf(dcx), 1e-7f));
        P[k][1] = 2.f*logf(fmaxf(fabsf(dcy), 1e-7f));
        P[k][2] = 2.f*logf(fmaxf(fabsf(dwx), 1e-7f));
        P[k][3] = 2.f*logf(fmaxf(fabsf(dwy), 1e-7f));
    }
    __syncthreads();

    for (int item = tid; item < TOPK*64; item += blockDim.x){
        int k = item >> 6, m = item & 63;
        size_t base = (size_t)(g*TOPK + k)*DIM;
        if (MK[k] == 0.f){
            __nv_bfloat16 z = __float2bfloat16(0.f);
            #pragma unroll
            for (int s = 0; s < 4; s++){
                g_Fhi[base + s*64 + m] = z; g_Flo[base + s*64 + m] = z;
            }
        } else {
            float invt = exp2f(-(float)m * 0.20762050593045977f);
            float v[4];
            v[0] = sinpif(P[k][0]*invt);
            v[1] = cospif(P[k][1]*invt);
            v[2] = sinpif(P[k][2]*invt);
            v[3] = cospif(P[k][3]*invt);
            #pragma unroll
            for (int s = 0; s < 4; s++){
                __nv_bfloat16 h, l; bsplit(v[s], h, l);
                g_Fhi[base + s*64 + m] = h; g_Flo[base + s*64 + m] = l;
            }
        }
    }
}

// ---------------------------------------------------------------- tgt gather+split
__global__ void conv3_kernel(const float* __restrict__ tgt){
    int g = blockIdx.x;
    if (g >= g_cnt) return;
    int c = threadIdx.x;
    float v = tgt[(size_t)g_list[g]*DIM + c];
    __nv_bfloat16 h, l; bsplit(v, h, l);
    g_A3hi[(size_t)g*DIM + c] = h;
    g_A3lo[(size_t)g*DIM + c] = l;
}

// ---------------------------------------------------------------- masked max over K
__global__ void agg_kernel(){
    int g = blockIdx.x;
    if (g >= g_cnt) return;
    int c = threadIdx.x;
    float best = g_Fe[(size_t)(g*TOPK)*DIM + c];
    #pragma unroll
    for (int k = 1; k < TOPK; k++)
        best = fmaxf(best, g_Fe[(size_t)(g*TOPK + k)*DIM + c]);
    g_AG[(size_t)g*DIM + c] = best;
}

// ---------------------------------------------------------------- mma.sync GEMM
// 128x128 tile/CTA, K=256 in 8 chunks of 32 bf16, bf16x3 compensated,
// cp.async double-buffered smem, 8 warps (2m x 4n), warp tile 64x32.
// ASEL: 1=F 2=H 3=A3 4=T1 5=CT ; BIDX weight idx ; EPI 1..5
template<int ASEL, int BIDX, int EPI, int ROWMULT>
__global__ void __launch_bounds__(256) gemm_mma(const float* __restrict__ bias,
                                                float* __restrict__ extOut){
    int rows = g_cnt * ROWMULT;
    int m0 = blockIdx.x * 128;
    if (m0 >= rows) return;
    int n0 = blockIdx.y * 128;

    const __nv_bfloat16 *Ahi, *Alo;
    if (ASEL==1){ Ahi=g_Fhi;  Alo=g_Flo;  }
    else if (ASEL==2){ Ahi=g_Hhi;  Alo=g_Hlo;  }
    else if (ASEL==3){ Ahi=g_A3hi; Alo=g_A3lo; }
    else if (ASEL==4){ Ahi=g_T1hi; Alo=g_T1lo; }
    else             { Ahi=g_CThi; Alo=g_CTlo; }
    const __nv_bfloat16* Bhi = g_Bwhi + (size_t)BIDX*DIM*DIM;
    const __nv_bfloat16* Blo = g_Bwlo + (size_t)BIDX*DIM*DIM;

    extern __shared__ char sm[];
    uint32_t sbase = smem_u32(sm);

    int tid  = threadIdx.x;
    int lane = tid & 31, warp = tid >> 5;
    int wm = warp >> 2, wn = warp & 3;

    // ---- cp.async issue for one chunk into buffer buf
    auto issue = [&](int ch, int buf){
        int k0 = ch * 32;
        uint32_t sb = sbase + buf*BUF_BYTES;
        #pragma unroll
        for (int h = 0; h < 2; h++){
            int s = tid + h*256;            // 0..511
            int row = s >> 2, c = s & 3;    // row 0..127, 16B seg 0..3
            uint32_t so = (uint32_t)(row*80 + c*16);
            size_t ga = (size_t)(m0 + row)*DIM + k0 + c*8;
            size_t gb = (size_t)(n0 + row)*DIM + k0 + c*8;
            cp_async16(sb + 0*TILE_BYTES + so, Ahi + ga);
            cp_async16(sb + 1*TILE_BYTES + so, Alo + ga);
            cp_async16(sb + 2*TILE_BYTES + so, Bhi + gb);
            cp_async16(sb + 3*TILE_BYTES + so, Blo + gb);
        }
        cp_commit();
    };

    float acc[4][4][4];
    #pragma unroll
    for (int i = 0; i < 4; i++)
        #pragma unroll
        for (int j = 0; j < 4; j++)
            #pragma unroll
            for (int q = 0; q < 4; q++) acc[i][j][q] = 0.f;

    issue(0, 0);
    for (int ch = 0; ch < 8; ch++){
        if (ch < 7){ issue(ch+1, (ch+1)&1); cp_wait<1>(); }
        else       { cp_wait<0>(); }
        __syncthreads();

        uint32_t sb = sbase + (ch&1)*BUF_BYTES;
        #pragma unroll
        for (int kk = 0; kk < 2; kk++){
            uint32_t a_hi[4][4], a_lo[4][4];
            #pragma unroll
            for (int mt = 0; mt < 4; mt++){
                uint32_t ad = sb + (uint32_t)((wm*64 + mt*16 + (lane & 15))*80
                                              + (kk*16 + ((lane >> 4) << 3))*2);
                LDMATRIX_X4(a_hi[mt], ad);
                LDMATRIX_X4(a_lo[mt], ad + TILE_BYTES);
            }
            uint32_t b_hi[4][2], b_lo[4][2];
            int ln = lane & 15;
            #pragma unroll
            for (int nt = 0; nt < 4; nt++){
                uint32_t bd = sb + 2*TILE_BYTES
                            + (uint32_t)((wn*32 + nt*8 + (ln & 7))*80
                                         + (kk*16 + ((ln >> 3) << 3))*2);
                LDMATRIX_X2(b_hi[nt], bd);
                LDMATRIX_X2(b_lo[nt], bd + TILE_BYTES);
            }
            #pragma unroll
            for (int mt = 0; mt < 4; mt++)
                #pragma unroll
                for (int nt = 0; nt < 4; nt++){
                    MMA_BF16(acc[mt][nt], a_hi[mt], b_hi[nt]);
                    MMA_BF16(acc[mt][nt], a_lo[mt], b_hi[nt]);
                    MMA_BF16(acc[mt][nt], a_hi[mt], b_lo[nt]);
                }
        }
        __syncthreads();
    }

    // ---- epilogue
    auto epil = [&](int m, int n, float v0, float v1){
        if (m >= rows) return;
        v0 += bias[n]; v1 += bias[n+1];
        if (EPI == 1){
            float o = g_overs[m];
            v0 = fmaxf(v0 + o*g_w3sum[n],   0.f);
            v1 = fmaxf(v1 + o*g_w3sum[n+1], 0.f);
            __nv_bfloat16 h0,l0,h1,l1; bsplit(v0,h0,l0); bsplit(v1,h1,l1);
            __nv_bfloat162 hh; hh.x=h0; hh.y=h1;
            __nv_bfloat162 ll; ll.x=l0; ll.y=l1;
            *(__nv_bfloat162*)(g_Hhi + (size_t)m*DIM + n) = hh;
            *(__nv_bfloat162*)(g_Hlo + (size_t)m*DIM + n) = ll;
        } else if (EPI == 2){
            float nk = g_nmk[m];
            float2 r; r.x = v0*nk; r.y = v1*nk;
            *(float2*)(g_Fe + (size_t)m*DIM + n) = r;
        } else if (EPI == 3){
            v0 = fmaxf(v0, 0.f); v1 = fmaxf(v1, 0.f);
            __nv_bfloat16 h0,l0,h1,l1; bsplit(v0,h0,l0); bsplit(v1,h1,l1);
            __nv_bfloat162 hh; hh.x=h0; hh.y=h1;
            __nv_bfloat162 ll; ll.x=l0; ll.y=l1;
            *(__nv_bfloat162*)(g_T1hi + (size_t)m*DIM + n) = hh;
            *(__nv_bfloat162*)(g_T1lo + (size_t)m*DIM + n) = ll;
        } else if (EPI == 4){
            float2 ag = *(const float2*)(g_AG + (size_t)m*DIM + n);
            v0 += ag.x; v1 += ag.y;
            __nv_bfloat16 h0,l0,h1,l1; bsplit(v0,h0,l0); bsplit(v1,h1,l1);
            __nv_bfloat162 hh; hh.x=h0; hh.y=h1;
            __nv_bfloat162 ll; ll.x=l0; ll.y=l1;
            *(__nv_bfloat162*)(g_CThi + (size_t)m*DIM + n) = hh;
            *(__nv_bfloat162*)(g_CTlo + (size_t)m*DIM + n) = ll;
        } else {
            float2 r; r.x = fmaxf(v0, 0.f); r.y = fmaxf(v1, 0.f);
            *(float2*)(extOut + (size_t)g_list[m]*DIM + n) = r;
        }
    };

    #pragma unroll
    for (int mt = 0; mt < 4; mt++){
        int r0 = m0 + wm*64 + mt*16 + (lane >> 2);
        #pragma unroll
        for (int nt = 0; nt < 4; nt++){
            int n = n0 + wn*32 + nt*8 + 2*(lane & 3);
            epil(r0,     n, acc[mt][nt][0], acc[mt][nt][1]);
            epil(r0 + 8, n, acc[mt][nt][2], acc[mt][nt][3]);
        }
    }
}

// ---------------------------------------------------------------- launch
extern "C" void kernel_launch(void* const* d_in, const int* in_sizes, int n_in,
                              void* d_out, int out_size){
    const float* tgt    = (const float*)d_in[0];
    const float* ious   = (const float*)d_in[1];
    const float* bboxes = (const float*)d_in[2];
    const float* gmask  = (const float*)d_in[3];
    const float* W1 = (const float*)d_in[4];  const float* b1 = (const float*)d_in[5];
    const float* W2 = (const float*)d_in[6];  const float* b2 = (const float*)d_in[7];
    const float* W3 = (const float*)d_in[8];  const float* b3 = (const float*)d_in[9];
    const float* W4 = (const float*)d_in[10]; const float* b4 = (const float*)d_in[11];
    const float* W5 = (const float*)d_in[12]; const float* b5 = (const float*)d_in[13];
    float* out = (float*)d_out;
    (void)in_sizes; (void)n_in; (void)out_size;

    cudaFuncSetAttribute(gemm_mma<1,2,1,TOPK>, cudaFuncAttributeMaxDynamicSharedMemorySize, SMEM_SZ);
    cudaFuncSetAttribute(gemm_mma<2,3,2,TOPK>, cudaFuncAttributeMaxDynamicSharedMemorySize, SMEM_SZ);
    cudaFuncSetAttribute(gemm_mma<3,0,3,1>,    cudaFuncAttributeMaxDynamicSharedMemorySize, SMEM_SZ);
    cudaFuncSetAttribute(gemm_mma<4,1,4,1>,    cudaFuncAttributeMaxDynamicSharedMemorySize, SMEM_SZ);
    cudaFuncSetAttribute(gemm_mma<5,4,5,1>,    cudaFuncAttributeMaxDynamicSharedMemorySize, SMEM_SZ);

    zero_kernel<<<NROWS, 256>>>(out);                 // resets g_cnt too
    prep_kernel<<<dim3(DIM,5), 256>>>(W1, W2, W3, W4, W5);
    w3sum_kernel<<<1, 256>>>(W3);
    topk_kernel<<<NQ, 256>>>(ious, gmask);
    feat_kernel<<<NROWS, 256>>>(bboxes);
    conv3_kernel<<<NROWS, 256>>>(tgt);

    dim3 gBig  ((MAXM  + 127)/128, 2);   // 563 x 2
    dim3 gSmall((NROWS + 127)/128, 2);   // 57 x 2

    // H = relu(F @ W3f + b3 + overs*w3sum)
    gemm_mma<1,2,1,TOPK><<<gBig, 256, SMEM_SZ>>>(b3, nullptr);
    // Fe = (H @ W4 + b4) * mk
    gemm_mma<2,3,2,TOPK><<<gBig, 256, SMEM_SZ>>>(b4, nullptr);
    // AG = max_k Fe
    agg_kernel<<<NROWS, 256>>>();
    // T1 = relu(tgt[list] @ W1 + b1)
    gemm_mma<3,0,3,1><<<gSmall, 256, SMEM_SZ>>>(b1, nullptr);
    // CT = T1 @ W2 + b2 + AG
    gemm_mma<4,1,4,1><<<gSmall, 256, SMEM_SZ>>>(b2, nullptr);
    // out[list] = relu(CT @ W5 + b5)
    gemm_mma<5,4,5,1><<<gSmall, 256, SMEM_SZ>>>(b5, out);
}

// round 4
// speedup vs baseline: 2.0107x; 1.0584x over previous
#include <cuda_runtime.h>
#include <cuda_bf16.h>
#include <math.h>
#include <stdint.h>

// ---------------------------------------------------------------- constants
#define BSZ   8
#define NQ    900
#define DIM   256
#define TOPK  10
#define NROWS (BSZ*NQ)            // 7200
#define MAXM  (NROWS*TOPK)        // 72000
#define MAXM_PAD  72064           // 563*128
#define NROWS_PAD 7296            // 57*128

#define A_TILE_BYTES 10240        // 128 rows * 80B (32 bf16 + pad)
#define SMEM_128 81920            // 2 * (2*10240 + 2*10240)
#define SMEM_256 122880           // 2 * (2*10240 + 2*20480)

// ---------------------------------------------------------------- scratch
__device__ int   g_cnt;
__device__ int   g_list[NROWS];
__device__ int   g_nidx[MAXM];
__device__ float g_niou[MAXM];
__device__ float g_nmk [MAXM];
__device__ float g_overs[MAXM];
__device__ float g_w3sum[DIM];

__device__ __nv_bfloat16 g_Bwhi[5*DIM*DIM];  // weights [w][n][k] K-major
__device__ __nv_bfloat16 g_Bwlo[5*DIM*DIM];

__device__ __nv_bfloat16 g_Fhi [(size_t)MAXM_PAD*DIM];
__device__ __nv_bfloat16 g_Flo [(size_t)MAXM_PAD*DIM];
__device__ __nv_bfloat16 g_Hhi [(size_t)MAXM_PAD*DIM];
__device__ __nv_bfloat16 g_Hlo [(size_t)MAXM_PAD*DIM];
__device__ __nv_bfloat16 g_A3hi[(size_t)NROWS_PAD*DIM];
__device__ __nv_bfloat16 g_A3lo[(size_t)NROWS_PAD*DIM];
__device__ __nv_bfloat16 g_T1hi[(size_t)NROWS_PAD*DIM];
__device__ __nv_bfloat16 g_T1lo[(size_t)NROWS_PAD*DIM];
__device__ __nv_bfloat16 g_CThi[(size_t)NROWS_PAD*DIM];
__device__ __nv_bfloat16 g_CTlo[(size_t)NROWS_PAD*DIM];
__device__ float g_Fe[(size_t)MAXM*DIM];
__device__ float g_AG[(size_t)NROWS*DIM];

// ---------------------------------------------------------------- helpers
static __device__ __forceinline__ uint32_t smem_u32(const void* p){
    uint32_t a;
    asm("{ .reg .u64 t; cvta.to.shared.u64 t, %1; cvt.u32.u64 %0, t; }" : "=r"(a) : "l"(p));
    return a;
}
static __device__ __forceinline__ void cp_async16(uint32_t s, const void* g){
    asm volatile("cp.async.ca.shared.global [%0], [%1], 16;" :: "r"(s), "l"(g));
}
static __device__ __forceinline__ void cp_commit(){
    asm volatile("cp.async.commit_group;");
}
template<int N> static __device__ __forceinline__ void cp_wait(){
    asm volatile("cp.async.wait_group %0;" :: "n"(N));
}
#define LDMATRIX_X4(r, addr) \
    asm volatile("ldmatrix.sync.aligned.m8n8.x4.shared.b16 {%0,%1,%2,%3}, [%4];" \
        : "=r"((r)[0]), "=r"((r)[1]), "=r"((r)[2]), "=r"((r)[3]) : "r"(addr))
#define LDMATRIX_X2(r, addr) \
    asm volatile("ldmatrix.sync.aligned.m8n8.x2.shared.b16 {%0,%1}, [%2];" \
        : "=r"((r)[0]), "=r"((r)[1]) : "r"(addr))
#define MMA_BF16(c, a, b) \
    asm volatile("mma.sync.aligned.m16n8k16.row.col.f32.bf16.bf16.f32 " \
        "{%0,%1,%2,%3}, {%4,%5,%6,%7}, {%8,%9}, {%0,%1,%2,%3};" \
        : "+f"((c)[0]), "+f"((c)[1]), "+f"((c)[2]), "+f"((c)[3]) \
        : "r"((a)[0]), "r"((a)[1]), "r"((a)[2]), "r"((a)[3]), "r"((b)[0]), "r"((b)[1]))

static __device__ __forceinline__ void bsplit(float v, __nv_bfloat16& h, __nv_bfloat16& l){
    h = __float2bfloat16(v);
    l = __float2bfloat16(v - __bfloat162float(h));
}

// ---------------------------------------------------------------- zero + cnt
__global__ void zero_kernel(float* __restrict__ out){
    int i = blockIdx.x*blockDim.x + threadIdx.x;
    if (i == 0) g_cnt = 0;
    if (i < NROWS*DIM) out[i] = 0.f;
}

// ---------------------------------------------------------------- compact active rows
__global__ void compact_kernel(const float* __restrict__ gmask){
    int r = blockIdx.x*blockDim.x + threadIdx.x;
    if (r < NROWS && gmask[r] == 0.f){
        int p = atomicAdd(&g_cnt, 1);
        g_list[p] = r;
    }
}

// ---------------------------------------------------------------- weight prep
__global__ void prep_kernel(const float* __restrict__ W1, const float* __restrict__ W2,
                            const float* __restrict__ W3, const float* __restrict__ W4,
                            const float* __restrict__ W5){
    int k = threadIdx.x, n = blockIdx.x, w = blockIdx.y;
    const float* W = (w==0)?W1 : (w==1)?W2 : (w==2)?W3 : (w==3)?W4 : W5;
    float v;
    if (w == 2){
        int a = k>>7, s = (k>>6)&1, m = k&63;
        int j = 64 + a*256 + s*128 + 2*m;
        v = W[j*DIM + n] + W[(j+1)*DIM + n];
    } else {
        v = W[k*DIM + n];
    }
    __nv_bfloat16 h, l; bsplit(v, h, l);
    g_Bwhi[(size_t)w*DIM*DIM + n*DIM + k] = h;
    g_Bwlo[(size_t)w*DIM*DIM + n*DIM + k] = l;
}
__global__ void w3sum_kernel(const float* __restrict__ W3){
    int n = threadIdx.x;
    float s = 0.f;
    #pragma unroll 16
    for (int q = 0; q < 64; q++) s += W3[q*DIM + n];
    g_w3sum[n] = s;
}

// ---------------------------------------------------------------- top-K (compacted rows)
__global__ void topk_kernel(const float* __restrict__ ious,
                            const float* __restrict__ gmask){
    int warp = threadIdx.x >> 5, lane = threadIdx.x & 31;
    int g = blockIdx.x*8 + warp;
    if (g >= g_cnt) return;
    int r = g_list[g];
    int b = r / NQ;
    const float4* row4 = (const float4*)(ious + (size_t)r*NQ);
    const float4* m4   = (const float4*)(gmask + (size_t)b*NQ);

    unsigned long long loc[TOPK];
    #pragma unroll
    for (int t = 0; t < TOPK; t++) loc[t] = 0ull;
    float thresh = 0.f;

    // NQ/4 == 225 float4 per row
    for (int q = lane; q < 225; q += 32){
        float4 iv = row4[q];
        float4 mv = m4[q];
        float v[4];
        v[0] = iv.x*mv.x; v[1] = iv.y*mv.y; v[2] = iv.z*mv.z; v[3] = iv.w*mv.w;
        #pragma unroll
        for (int x = 0; x < 4; x++){
            if (v[x] >= thresh){
                unsigned long long key =
                    ((unsigned long long)__float_as_uint(v[x]) << 32) |
                    (unsigned)(0xFFFFFFFFu - (unsigned)(4*q + x));
                if (key > loc[TOPK-1]){
                    loc[TOPK-1] = key;
                    #pragma unroll
                    for (int t = TOPK-1; t > 0; t--)
                        if (loc[t] > loc[t-1]){
                            unsigned long long tmp = loc[t-1]; loc[t-1] = loc[t]; loc[t] = tmp;
                        }
                    thresh = __uint_as_float((unsigned)(loc[TOPK-1] >> 32));
                }
            }
        }
    }

    const float* mrow = gmask + (size_t)b*NQ;
    for (int t = 0; t < TOPK; t++){
        unsigned long long cand = loc[0];
        unsigned long long best = cand;
        #pragma unroll
        for (int o = 16; o > 0; o >>= 1){
            unsigned long long oth = __shfl_xor_sync(0xffffffffu, best, o);
            if (oth > best) best = oth;
        }
        if (cand == best){
            #pragma unroll
            for (int t2 = 0; t2 < TOPK-1; t2++) loc[t2] = loc[t2+1];
            loc[TOPK-1] = 0ull;
        }
        if (lane == 0){
            unsigned j = 0xFFFFFFFFu - (unsigned)(best & 0xFFFFFFFFull);
            float v = __uint_as_float((unsigned)(best >> 32));
            g_nidx[g*TOPK + t] = b*NQ + (int)j;
            g_niou[g*TOPK + t] = v;
            g_nmk [g*TOPK + t] = (mrow[j] != 0.f && v >= 0.4f) ? 1.f : 0.f;
        }
    }
}

// ---------------------------------------------------------------- features (bf16 hi/lo)
__global__ void feat_kernel(const float* __restrict__ bboxes){
    int g = blockIdx.x;
    if (g >= g_cnt) return;
    int tid = threadIdx.x;
    __shared__ float P[TOPK][4];
    __shared__ float MK[TOPK];

    if (tid < TOPK){
        int k = tid;
        int srow = g_list[g];
        float4 sb = *(const float4*)(bboxes + (size_t)srow*4);
        int nrow = g_nidx[g*TOPK + k];
        float4 nb = *(const float4*)(bboxes + (size_t)nrow*4);
        float mkv = g_nmk[g*TOPK + k];
        MK[k] = mkv;
        g_overs[g*TOPK + k] = g_niou[g*TOPK + k] * mkv;
        float dcx = 0.5f*(nb.x+nb.z) - 0.5f*(sb.x+sb.z);
        float dcy = 0.5f*(nb.y+nb.w) - 0.5f*(sb.y+sb.w);
        float dwx = (nb.z-nb.x) - (sb.z-sb.x);
        float dwy = (nb.w-nb.y) - (sb.w-sb.y);
        P[k][0] = 2.f*logf(fmaxf(fabsf(dcx), 1e-7f));
        P[k][1] = 2.f*logf(fmaxf(fabsf(dcy), 1e-7f));
        P[k][2] = 2.f*logf(fmaxf(fabsf(dwx), 1e-7f));
        P[k][3] = 2.f*logf(fmaxf(fabsf(dwy), 1e-7f));
    }
    __syncthreads();

    for (int item = tid; item < TOPK*64; item += blockDim.x){
        int k = item >> 6, m = item & 63;
        size_t base = (size_t)(g*TOPK + k)*DIM;
        if (MK[k] == 0.f){
            __nv_bfloat16 z = __float2bfloat16(0.f);
            #pragma unroll
            for (int s = 0; s < 4; s++){
                g_Fhi[base + s*64 + m] = z; g_Flo[base + s*64 + m] = z;
            }
        } else {
            float invt = exp2f(-(float)m * 0.20762050593045977f);
            float v[4];
            v[0] = sinpif(P[k][0]*invt);
            v[1] = cospif(P[k][1]*invt);
            v[2] = sinpif(P[k][2]*invt);
            v[3] = cospif(P[k][3]*invt);
            #pragma unroll
            for (int s = 0; s < 4; s++){
                __nv_bfloat16 h, l; bsplit(v[s], h, l);
                g_Fhi[base + s*64 + m] = h; g_Flo[base + s*64 + m] = l;
            }
        }
    }
}

// ---------------------------------------------------------------- tgt gather+split
__global__ void conv3_kernel(const float* __restrict__ tgt){
    int g = blockIdx.x;
    if (g >= g_cnt) return;
    int c = threadIdx.x;
    float v = tgt[(size_t)g_list[g]*DIM + c];
    __nv_bfloat16 h, l; bsplit(v, h, l);
    g_A3hi[(size_t)g*DIM + c] = h;
    g_A3lo[(size_t)g*DIM + c] = l;
}

// ---------------------------------------------------------------- masked max over K
__global__ void agg_kernel(){
    int g = blockIdx.x;
    if (g >= g_cnt) return;
    int c = threadIdx.x;
    float best = g_Fe[(size_t)(g*TOPK)*DIM + c];
    #pragma unroll
    for (int k = 1; k < TOPK; k++)
        best = fmaxf(best, g_Fe[(size_t)(g*TOPK + k)*DIM + c]);
    g_AG[(size_t)g*DIM + c] = best;
}

// ---------------------------------------------------------------- mma.sync GEMM
// 128 x NTILE tile/CTA, K=256 in 8 chunks of 32, bf16x3 compensated,
// cp.async double-buffered. NTILE=128: 256 thr (2x4 warps); 256: 512 thr (2x8).
template<int ASEL, int BIDX, int EPI, int ROWMULT, int NTILE>
__global__ void __launch_bounds__((NTILE==256)?512:256)
gemm_mma(const float* __restrict__ bias, float* __restrict__ extOut){
    constexpr int THREADS = (NTILE==256)?512:256;
    constexpr int NWARP_N = NTILE/32;
    constexpr int BT_BYTES = NTILE*80;
    constexpr int BUFB = 2*A_TILE_BYTES + 2*BT_BYTES;

    int rows = g_cnt * ROWMULT;
    int m0 = blockIdx.x * 128;
    if (m0 >= rows) return;
    int n0 = blockIdx.y * NTILE;

    const __nv_bfloat16 *Ahi, *Alo;
    if (ASEL==1){ Ahi=g_Fhi;  Alo=g_Flo;  }
    else if (ASEL==2){ Ahi=g_Hhi;  Alo=g_Hlo;  }
    else if (ASEL==3){ Ahi=g_A3hi; Alo=g_A3lo; }
    else if (ASEL==4){ Ahi=g_T1hi; Alo=g_T1lo; }
    else             { Ahi=g_CThi; Alo=g_CTlo; }
    const __nv_bfloat16* Bhi = g_Bwhi + (size_t)BIDX*DIM*DIM;
    const __nv_bfloat16* Blo = g_Bwlo + (size_t)BIDX*DIM*DIM;

    extern __shared__ char sm[];
    uint32_t sbase = smem_u32(sm);

    int tid  = threadIdx.x;
    int lane = tid & 31, warp = tid >> 5;
    int wm = warp / NWARP_N, wn = warp % NWARP_N;

    auto issue = [&](int ch, int buf){
        int k0 = ch * 32;
        uint32_t sb = sbase + buf*BUFB;
        #pragma unroll
        for (int s = tid; s < 512; s += THREADS){
            int row = s >> 2, c = s & 3;
            uint32_t so = (uint32_t)(row*80 + c*16);
            size_t ga = (size_t)(m0 + row)*DIM + k0 + c*8;
            cp_async16(sb + so, Ahi + ga);
            cp_async16(sb + A_TILE_BYTES + so, Alo + ga);
        }
        #pragma unroll
        for (int s = tid; s < NTILE*4; s += THREADS){
            int row = s >> 2, c = s & 3;
            uint32_t so = (uint32_t)(row*80 + c*16);
            size_t gb = (size_t)(n0 + row)*DIM + k0 + c*8;
            cp_async16(sb + 2*A_TILE_BYTES + so, Bhi + gb);
            cp_async16(sb + 2*A_TILE_BYTES + BT_BYTES + so, Blo + gb);
        }
        cp_commit();
    };

    float acc[4][4][4];
    #pragma unroll
    for (int i = 0; i < 4; i++)
        #pragma unroll
        for (int j = 0; j < 4; j++)
            #pragma unroll
            for (int q = 0; q < 4; q++) acc[i][j][q] = 0.f;

    issue(0, 0);
    for (int ch = 0; ch < 8; ch++){
        if (ch < 7){ issue(ch+1, (ch+1)&1); cp_wait<1>(); }
        else       { cp_wait<0>(); }
        __syncthreads();

        uint32_t sb = sbase + (ch&1)*BUFB;
        #pragma unroll
        for (int kk = 0; kk < 2; kk++){
            uint32_t a_hi[4][4], a_lo[4][4];
            #pragma unroll
            for (int mt = 0; mt < 4; mt++){
                uint32_t ad = sb + (uint32_t)((wm*64 + mt*16 + (lane & 15))*80
                                              + (kk*16 + ((lane >> 4) << 3))*2);
                LDMATRIX_X4(a_hi[mt], ad);
                LDMATRIX_X4(a_lo[mt], ad + A_TILE_BYTES);
            }
            uint32_t b_hi[4][2], b_lo[4][2];
            int ln = lane & 15;
            #pragma unroll
            for (int nt = 0; nt < 4; nt++){
                uint32_t bd = sb + 2*A_TILE_BYTES
                            + (uint32_t)((wn*32 + nt*8 + (ln & 7))*80
                                         + (kk*16 + ((ln >> 3) << 3))*2);
                LDMATRIX_X2(b_hi[nt], bd);
                LDMATRIX_X2(b_lo[nt], bd + BT_BYTES);
            }
            #pragma unroll
            for (int mt = 0; mt < 4; mt++)
                #pragma unroll
                for (int nt = 0; nt < 4; nt++){
                    MMA_BF16(acc[mt][nt], a_hi[mt], b_hi[nt]);
                    MMA_BF16(acc[mt][nt], a_lo[mt], b_hi[nt]);
                    MMA_BF16(acc[mt][nt], a_hi[mt], b_lo[nt]);
                }
        }
        __syncthreads();
    }

    // ---- epilogue
    auto epil = [&](int m, int n, float v0, float v1){
        if (m >= rows) return;
        v0 += bias[n]; v1 += bias[n+1];
        if (EPI == 1){
            float o = g_overs[m];
            v0 = fmaxf(v0 + o*g_w3sum[n],   0.f);
            v1 = fmaxf(v1 + o*g_w3sum[n+1], 0.f);
            __nv_bfloat16 h0,l0,h1,l1; bsplit(v0,h0,l0); bsplit(v1,h1,l1);
            __nv_bfloat162 hh; hh.x=h0; hh.y=h1;
            __nv_bfloat162 ll; ll.x=l0; ll.y=l1;
            *(__nv_bfloat162*)(g_Hhi + (size_t)m*DIM + n) = hh;
            *(__nv_bfloat162*)(g_Hlo + (size_t)m*DIM + n) = ll;
        } else if (EPI == 2){
            float nk = g_nmk[m];
            float2 r; r.x = v0*nk; r.y = v1*nk;
            *(float2*)(g_Fe + (size_t)m*DIM + n) = r;
        } else if (EPI == 3){
            v0 = fmaxf(v0, 0.f); v1 = fmaxf(v1, 0.f);
            __nv_bfloat16 h0,l0,h1,l1; bsplit(v0,h0,l0); bsplit(v1,h1,l1);
            __nv_bfloat162 hh; hh.x=h0; hh.y=h1;
            __nv_bfloat162 ll; ll.x=l0; ll.y=l1;
            *(__nv_bfloat162*)(g_T1hi + (size_t)m*DIM + n) = hh;
            *(__nv_bfloat162*)(g_T1lo + (size_t)m*DIM + n) = ll;
        } else if (EPI == 4){
            float2 ag = *(const float2*)(g_AG + (size_t)m*DIM + n);
            v0 += ag.x; v1 += ag.y;
            __nv_bfloat16 h0,l0,h1,l1; bsplit(v0,h0,l0); bsplit(v1,h1,l1);
            __nv_bfloat162 hh; hh.x=h0; hh.y=h1;
            __nv_bfloat162 ll; ll.x=l0; ll.y=l1;
            *(__nv_bfloat162*)(g_CThi + (size_t)m*DIM + n) = hh;
            *(__nv_bfloat162*)(g_CTlo + (size_t)m*DIM + n) = ll;
        } else {
            float2 r; r.x = fmaxf(v0, 0.f); r.y = fmaxf(v1, 0.f);
            *(float2*)(extOut + (size_t)g_list[m]*DIM + n) = r;
        }
    };

    #pragma unroll
    for (int mt = 0; mt < 4; mt++){
        int r0 = m0 + wm*64 + mt*16 + (lane >> 2);
        #pragma unroll
        for (int nt = 0; nt < 4; nt++){
            int n = n0 + wn*32 + nt*8 + 2*(lane & 3);
            epil(r0,     n, acc[mt][nt][0], acc[mt][nt][1]);
            epil(r0 + 8, n, acc[mt][nt][2], acc[mt][nt][3]);
        }
    }
}

// ---------------------------------------------------------------- launch
extern "C" void kernel_launch(void* const* d_in, const int* in_sizes, int n_in,
                              void* d_out, int out_size){
    const float* tgt    = (const float*)d_in[0];
    const float* ious   = (const float*)d_in[1];
    const float* bboxes = (const float*)d_in[2];
    const float* gmask  = (const float*)d_in[3];
    const float* W1 = (const float*)d_in[4];  const float* b1 = (const float*)d_in[5];
    const float* W2 = (const float*)d_in[6];  const float* b2 = (const float*)d_in[7];
    const float* W3 = (const float*)d_in[8];  const float* b3 = (const float*)d_in[9];
    const float* W4 = (const float*)d_in[10]; const float* b4 = (const float*)d_in[11];
    const float* W5 = (const float*)d_in[12]; const float* b5 = (const float*)d_in[13];
    float* out = (float*)d_out;
    (void)in_sizes; (void)n_in; (void)out_size;

    cudaFuncSetAttribute(gemm_mma<1,2,1,TOPK,256>, cudaFuncAttributeMaxDynamicSharedMemorySize, SMEM_256);
    cudaFuncSetAttribute(gemm_mma<2,3,2,TOPK,256>, cudaFuncAttributeMaxDynamicSharedMemorySize, SMEM_256);
    cudaFuncSetAttribute(gemm_mma<3,0,3,1,128>,    cudaFuncAttributeMaxDynamicSharedMemorySize, SMEM_128);
    cudaFuncSetAttribute(gemm_mma<4,1,4,1,128>,    cudaFuncAttributeMaxDynamicSharedMemorySize, SMEM_128);
    cudaFuncSetAttribute(gemm_mma<5,4,5,1,128>,    cudaFuncAttributeMaxDynamicSharedMemorySize, SMEM_128);

    zero_kernel<<<NROWS, 256>>>(out);                 // resets g_cnt
    compact_kernel<<<(NROWS+255)/256, 256>>>(gmask);
    prep_kernel<<<dim3(DIM,5), 256>>>(W1, W2, W3, W4, W5);
    w3sum_kernel<<<1, 256>>>(W3);
    topk_kernel<<<NQ, 256>>>(ious, gmask);
    feat_kernel<<<NROWS, 256>>>(bboxes);
    conv3_kernel<<<NROWS, 256>>>(tgt);

    int gBig = (MAXM + 127)/128;         // 563
    dim3 gSmall((NROWS + 127)/128, 2);   // 57 x 2

    // H = relu(F @ W3f + b3 + overs*w3sum)
    gemm_mma<1,2,1,TOPK,256><<<gBig, 512, SMEM_256>>>(b3, nullptr);
    // Fe = (H @ W4 + b4) * mk
    gemm_mma<2,3,2,TOPK,256><<<gBig, 512, SMEM_256>>>(b4, nullptr);
    // AG = max_k Fe
    agg_kernel<<<NROWS, 256>>>();
    // T1 = relu(tgt[list] @ W1 + b1)
    gemm_mma<3,0,3,1,128><<<gSmall, 256, SMEM_128>>>(b1, nullptr);
    // CT = T1 @ W2 + b2 + AG
    gemm_mma<4,1,4,1,128><<<gSmall, 256, SMEM_128>>>(b2, nullptr);
    // out[list] = relu(CT @ W5 + b5)
    gemm_mma<5,4,5,1,128><<<gSmall, 256, SMEM_128>>>(b5, out);
}